// round 4
// baseline (speedup 1.0000x reference)
#include <cuda_runtime.h>
#include <cuda_bf16.h>
#include <math.h>

// Problem constants
#define BB   32
#define NN   512
#define DIN  768
#define DOUT 256
#define MM   (BB * NN)          // 16384 rows
#define NEGV (-9.0e15f)
#define SLOPE 0.2f

// Scratch (device globals: allocation-free)
__device__ float g_Wh[(size_t)MM * DOUT];   // 16 MB
__device__ float g_s1[MM];
__device__ float g_s2[MM];

// ---------------------------------------------------------------------------
// Kernel A: Wh = h @ W + pos_table[positions]
// C[16384,256] = A[16384,768] * W[768,256]
// BLOCK_M=32, BK=32, 256 threads, thread tile 8x4.
// ---------------------------------------------------------------------------
__global__ void __launch_bounds__(256) k_gemm1(
    const float* __restrict__ h,
    const int*   __restrict__ positions,
    const float* __restrict__ W,
    const float* __restrict__ pos_table)
{
    __shared__ float hs[32][32];
    __shared__ float Ws[32][DOUT];

    const int row0 = blockIdx.x * 32;
    const int t  = threadIdx.x;
    const int tx = t & 63;        // col group: cols tx*4 .. tx*4+3
    const int ty = t >> 6;        // row group: rows ty*8 .. ty*8+7

    float acc[8][4] = {};

    for (int k0 = 0; k0 < DIN; k0 += 32) {
        // load h tile: 32x32 floats, 1 float4 per thread
        {
            const int e = t * 4;
            const int r = e >> 5;
            const int k = e & 31;
            float4 v = *reinterpret_cast<const float4*>(
                &h[(size_t)(row0 + r) * DIN + k0 + k]);
            *reinterpret_cast<float4*>(&hs[r][k]) = v;
        }
        // load W tile: 32x256 floats, 8 float4 per thread
        #pragma unroll
        for (int i = 0; i < 8; i++) {
            const int f = t + i * 256;      // float4 index in [0,2048)
            const int k = f >> 6;
            const int c = (f & 63) * 4;
            float4 v = *reinterpret_cast<const float4*>(
                &W[(size_t)(k0 + k) * DOUT + c]);
            *reinterpret_cast<float4*>(&Ws[k][c]) = v;
        }
        __syncthreads();

        #pragma unroll
        for (int k = 0; k < 32; k++) {
            float4 bv = *reinterpret_cast<const float4*>(&Ws[k][tx * 4]);
            #pragma unroll
            for (int i = 0; i < 8; i++) {
                const float av = hs[ty * 8 + i][k];
                acc[i][0] += av * bv.x;
                acc[i][1] += av * bv.y;
                acc[i][2] += av * bv.z;
                acc[i][3] += av * bv.w;
            }
        }
        __syncthreads();
    }

    // epilogue: add positional embedding, store Wh
    #pragma unroll
    for (int i = 0; i < 8; i++) {
        const int row = row0 + ty * 8 + i;
        const int p   = positions[row];
        const int c   = tx * 4;
        float4 pe = *reinterpret_cast<const float4*>(&pos_table[(size_t)p * DOUT + c]);
        float4 o;
        o.x = acc[i][0] + pe.x;
        o.y = acc[i][1] + pe.y;
        o.z = acc[i][2] + pe.z;
        o.w = acc[i][3] + pe.w;
        *reinterpret_cast<float4*>(&g_Wh[(size_t)row * DOUT + c]) = o;
    }
}

// ---------------------------------------------------------------------------
// Kernel S: s1[row] = Wh[row,:] . a1 ; s2[row] = Wh[row,:] . a2
// one warp per row
// ---------------------------------------------------------------------------
__global__ void __launch_bounds__(256) k_sdots(
    const float* __restrict__ a1,
    const float* __restrict__ a2)
{
    const int gwarp = (blockIdx.x * blockDim.x + threadIdx.x) >> 5;
    const int lane  = threadIdx.x & 31;
    if (gwarp >= MM) return;

    const float* wh = g_Wh + (size_t)gwarp * DOUT;
    float p1 = 0.f, p2 = 0.f;
    #pragma unroll
    for (int i = 0; i < 8; i++) {
        const int c = lane + i * 32;
        const float v = wh[c];
        p1 += v * a1[c];
        p2 += v * a2[c];
    }
    #pragma unroll
    for (int off = 16; off; off >>= 1) {
        p1 += __shfl_xor_sync(0xFFFFFFFFu, p1, off);
        p2 += __shfl_xor_sync(0xFFFFFFFFu, p2, off);
    }
    if (lane == 0) {
        g_s1[gwarp] = p1;
        g_s2[gwarp] = p2;
    }
}

// ---------------------------------------------------------------------------
// Kernel B: masked softmax + AV.  One block = (batch b, 8 attention rows).
// Warp w computes softmax of row i0+w fully inside the warp (no barriers),
// writes attention out, then all 256 threads do AV (thread t owns column t).
// ---------------------------------------------------------------------------
__global__ void __launch_bounds__(256) k_attn(
    const int* __restrict__ adj,
    float* __restrict__ out_hp,
    float* __restrict__ out_att)
{
    constexpr int TI = 8;
    __shared__ float s2s[NN];
    __shared__ float att[TI][NN];

    const int b  = blockIdx.x / (NN / TI);
    const int i0 = (blockIdx.x % (NN / TI)) * TI;
    const int t  = threadIdx.x;

    s2s[t]       = g_s2[b * NN + t];
    s2s[t + 256] = g_s2[b * NN + t + 256];
    __syncthreads();

    const int w = t >> 5, lane = t & 31;
    {
        const int i = i0 + w;
        const float s1v = g_s1[b * NN + i];
        const int* adjrow = adj + (size_t)(b * NN + i) * NN;

        float m = -INFINITY;
        #pragma unroll
        for (int jj = 0; jj < 16; jj++) {
            const int j = lane + jj * 32;
            const float x = s1v + s2s[j];
            const float e = x > 0.f ? x : SLOPE * x;
            const float v = (adjrow[j] > 0) ? e : NEGV;
            att[w][j] = v;
            m = fmaxf(m, v);
        }
        #pragma unroll
        for (int off = 16; off; off >>= 1)
            m = fmaxf(m, __shfl_xor_sync(0xFFFFFFFFu, m, off));

        float s = 0.f;
        #pragma unroll
        for (int jj = 0; jj < 16; jj++) {
            const int j = lane + jj * 32;
            const float ex = __expf(att[w][j] - m);
            att[w][j] = ex;
            s += ex;
        }
        #pragma unroll
        for (int off = 16; off; off >>= 1)
            s += __shfl_xor_sync(0xFFFFFFFFu, s, off);

        const float inv = 1.f / s;
        float* arow = out_att + (size_t)(b * NN + i) * NN;
        #pragma unroll
        for (int jj = 0; jj < 16; jj++) {
            const int j = lane + jj * 32;
            const float av = att[w][j] * inv;
            att[w][j] = av;
            arow[j] = av;
        }
    }
    __syncthreads();

    // AV: thread t owns output column d = t for all 8 rows
    float acc[TI] = {};
    const float* WhB = g_Wh + (size_t)b * NN * DOUT + t;
    #pragma unroll 4
    for (int j = 0; j < NN; j++) {
        const float wv = WhB[(size_t)j * DOUT];
        #pragma unroll
        for (int r = 0; r < TI; r++)
            acc[r] += att[r][j] * wv;
    }
    #pragma unroll
    for (int r = 0; r < TI; r++)
        out_hp[(size_t)(b * NN + i0 + r) * DOUT + t] = acc[r];
}

// ---------------------------------------------------------------------------
extern "C" void kernel_launch(void* const* d_in, const int* in_sizes, int n_in,
                              void* d_out, int out_size)
{
    const float* h         = (const float*)d_in[0];
    const int*   adj       = (const int*)  d_in[1];
    const int*   positions = (const int*)  d_in[2];
    const float* W         = (const float*)d_in[3];
    const float* a1        = (const float*)d_in[4];
    const float* a2        = (const float*)d_in[5];
    const float* pos_table = (const float*)d_in[6];

    float* out_hp  = (float*)d_out;                        // [B,N,DOUT]
    float* out_att = (float*)d_out + (size_t)MM * DOUT;    // [B,N,N]

    k_gemm1<<<MM / 32, 256>>>(h, positions, W, pos_table);
    k_sdots<<<MM / 8, 256>>>(a1, a2);
    k_attn<<<BB * (NN / 8), 256>>>(adj, out_hp, out_att);
}

// round 6
// speedup vs baseline: 1.5106x; 1.5106x over previous
#include <cuda_runtime.h>
#include <cuda_bf16.h>
#include <math.h>
#include <stdint.h>

// Problem constants
#define BB   32
#define NN   512
#define DIN  768
#define DOUT 256
#define MM   (BB * NN)          // 16384 rows
#define NEGV (-9.0e15f)
#define SLOPE 0.2f

// Scratch (device globals: allocation-free)
__device__ float g_Wh[(size_t)MM * DOUT];   // 16 MB
__device__ float g_s1[MM];
__device__ float g_s2[MM];

// ---------------------------------------------------------------------------
// tf32 helpers
// ---------------------------------------------------------------------------
__device__ __forceinline__ float to_tf32(float x) {
    asm("cvt.rna.tf32.f32 %0, %0;" : "+f"(x));
    return x;
}

__device__ __forceinline__ void mma_tf32(
    float c[4], unsigned a0, unsigned a1, unsigned a2, unsigned a3,
    unsigned b0, unsigned b1)
{
    asm volatile(
        "mma.sync.aligned.m16n8k8.row.col.f32.tf32.tf32.f32 "
        "{%0,%1,%2,%3}, {%4,%5,%6,%7}, {%8,%9}, {%0,%1,%2,%3};\n"
        : "+f"(c[0]), "+f"(c[1]), "+f"(c[2]), "+f"(c[3])
        : "r"(a0), "r"(a1), "r"(a2), "r"(a3), "r"(b0), "r"(b1));
}

// ---------------------------------------------------------------------------
// Kernel A: Wh = h @ W + pos_table[positions]  via tf32 tensor-core MMA
// C[16384,256] = A[16384,768] * W[768,256]
// BM=128 BN=128 BK=32, 256 threads = 8 warps (4 m x 2 n), warp tile 32x64.
// ---------------------------------------------------------------------------
#define BM 128
#define BN 128
#define BK 32
#define ASTRIDE 36     // BK + 4 : A-frag loads conflict-free (4*gid + tid4)
#define BSTRIDE 136    // BN + 8 : B-frag loads conflict-free (8*tid4 + gid)

__global__ void __launch_bounds__(256, 2) k_gemm1(
    const float* __restrict__ h,
    const int*   __restrict__ positions,
    const float* __restrict__ W,
    const float* __restrict__ pos_table)
{
    __shared__ float As[BM][ASTRIDE];   // 18432 B
    __shared__ float Bs[BK][BSTRIDE];   // 17408 B

    const int bx   = blockIdx.x;
    const int row0 = (bx >> 1) * BM;
    const int col0 = (bx & 1)  * BN;

    const int t    = threadIdx.x;
    const int wid  = t >> 5;
    const int lane = t & 31;
    const int gid  = lane >> 2;     // 0..7
    const int tid4 = lane & 3;      // 0..3

    const int wm = (wid & 3) * 32;  // warp m offset in tile
    const int wn = (wid >> 2) * 64; // warp n offset in tile

    float acc[2][8][4];
    #pragma unroll
    for (int i = 0; i < 2; i++)
        #pragma unroll
        for (int j = 0; j < 8; j++)
            #pragma unroll
            for (int q = 0; q < 4; q++)
                acc[i][j][q] = 0.f;

    // staging registers for the software pipeline
    float4 ar[4], br[4];

    // A tile element mapping: f = t + i*256 -> m = f/8, k4 = (f%8)*4
    // B tile element mapping: f = t + i*256 -> kr = f/32, n4 = (f%32)*4
    const int a_m  = t >> 3;          // base row for i=0 (rows advance by 32 per i)
    const int a_k4 = (t & 7) * 4;
    const int b_kr = t >> 5;          // base k row for i=0 (advance by 8 per i)
    const int b_n4 = (t & 31) * 4;

    // prime the pipeline: load tile 0
    {
        const int k0 = 0;
        #pragma unroll
        for (int i = 0; i < 4; i++) {
            ar[i] = *reinterpret_cast<const float4*>(
                &h[(size_t)(row0 + a_m + i * 32) * DIN + k0 + a_k4]);
            br[i] = *reinterpret_cast<const float4*>(
                &W[(size_t)(k0 + b_kr + i * 8) * DOUT + col0 + b_n4]);
        }
    }

    const int NTILES = DIN / BK;   // 24
    for (int tile = 0; tile < NTILES; tile++) {
        // stage (with tf32 rounding) into smem
        #pragma unroll
        for (int i = 0; i < 4; i++) {
            float4 v = ar[i];
            v.x = to_tf32(v.x); v.y = to_tf32(v.y);
            v.z = to_tf32(v.z); v.w = to_tf32(v.w);
            *reinterpret_cast<float4*>(&As[a_m + i * 32][a_k4]) = v;
            float4 w4 = br[i];
            w4.x = to_tf32(w4.x); w4.y = to_tf32(w4.y);
            w4.z = to_tf32(w4.z); w4.w = to_tf32(w4.w);
            *reinterpret_cast<float4*>(&Bs[b_kr + i * 8][b_n4]) = w4;
        }
        __syncthreads();

        // prefetch next tile while computing this one
        if (tile + 1 < NTILES) {
            const int k0 = (tile + 1) * BK;
            #pragma unroll
            for (int i = 0; i < 4; i++) {
                ar[i] = *reinterpret_cast<const float4*>(
                    &h[(size_t)(row0 + a_m + i * 32) * DIN + k0 + a_k4]);
                br[i] = *reinterpret_cast<const float4*>(
                    &W[(size_t)(k0 + b_kr + i * 8) * DOUT + col0 + b_n4]);
            }
        }

        // 4 k-steps of 8
        #pragma unroll
        for (int ks = 0; ks < 4; ks++) {
            const int k8 = ks * 8;
            unsigned af[2][4];
            #pragma unroll
            for (int ms = 0; ms < 2; ms++) {
                const int r = wm + ms * 16 + gid;
                af[ms][0] = __float_as_uint(As[r    ][k8 + tid4]);
                af[ms][1] = __float_as_uint(As[r + 8][k8 + tid4]);
                af[ms][2] = __float_as_uint(As[r    ][k8 + tid4 + 4]);
                af[ms][3] = __float_as_uint(As[r + 8][k8 + tid4 + 4]);
            }
            #pragma unroll
            for (int ns = 0; ns < 8; ns++) {
                const int c = wn + ns * 8 + gid;
                unsigned b0 = __float_as_uint(Bs[k8 + tid4    ][c]);
                unsigned b1 = __float_as_uint(Bs[k8 + tid4 + 4][c]);
                mma_tf32(acc[0][ns], af[0][0], af[0][1], af[0][2], af[0][3], b0, b1);
                mma_tf32(acc[1][ns], af[1][0], af[1][1], af[1][2], af[1][3], b0, b1);
            }
        }
        __syncthreads();
    }

    // epilogue: add positional embedding, store Wh
    #pragma unroll
    for (int ms = 0; ms < 2; ms++) {
        const int r0 = row0 + wm + ms * 16 + gid;
        const int r1 = r0 + 8;
        const int p0 = positions[r0];
        const int p1 = positions[r1];
        #pragma unroll
        for (int ns = 0; ns < 8; ns++) {
            const int c = col0 + wn + ns * 8 + tid4 * 2;
            float2 pe0 = *reinterpret_cast<const float2*>(&pos_table[(size_t)p0 * DOUT + c]);
            float2 pe1 = *reinterpret_cast<const float2*>(&pos_table[(size_t)p1 * DOUT + c]);
            float2 o0, o1;
            o0.x = acc[ms][ns][0] + pe0.x;
            o0.y = acc[ms][ns][1] + pe0.y;
            o1.x = acc[ms][ns][2] + pe1.x;
            o1.y = acc[ms][ns][3] + pe1.y;
            *reinterpret_cast<float2*>(&g_Wh[(size_t)r0 * DOUT + c]) = o0;
            *reinterpret_cast<float2*>(&g_Wh[(size_t)r1 * DOUT + c]) = o1;
        }
    }
}

// ---------------------------------------------------------------------------
// Kernel S: s1[row] = Wh[row,:] . a1 ; s2[row] = Wh[row,:] . a2
// one warp per row
// ---------------------------------------------------------------------------
__global__ void __launch_bounds__(256) k_sdots(
    const float* __restrict__ a1,
    const float* __restrict__ a2)
{
    const int gwarp = (blockIdx.x * blockDim.x + threadIdx.x) >> 5;
    const int lane  = threadIdx.x & 31;
    if (gwarp >= MM) return;

    const float* wh = g_Wh + (size_t)gwarp * DOUT;
    float p1 = 0.f, p2 = 0.f;
    #pragma unroll
    for (int i = 0; i < 8; i++) {
        const int c = lane + i * 32;
        const float v = wh[c];
        p1 += v * a1[c];
        p2 += v * a2[c];
    }
    #pragma unroll
    for (int off = 16; off; off >>= 1) {
        p1 += __shfl_xor_sync(0xFFFFFFFFu, p1, off);
        p2 += __shfl_xor_sync(0xFFFFFFFFu, p2, off);
    }
    if (lane == 0) {
        g_s1[gwarp] = p1;
        g_s2[gwarp] = p2;
    }
}

// ---------------------------------------------------------------------------
// Kernel B: masked softmax + AV.  One block = (batch b, 8 attention rows).
// Warp w computes softmax of row i0+w fully inside the warp (no barriers),
// writes attention out, then all 256 threads do AV (thread t owns column t).
// ---------------------------------------------------------------------------
__global__ void __launch_bounds__(256) k_attn(
    const int* __restrict__ adj,
    float* __restrict__ out_hp,
    float* __restrict__ out_att)
{
    constexpr int TI = 8;
    __shared__ float s2s[NN];
    __shared__ float att[TI][NN];

    const int b  = blockIdx.x / (NN / TI);
    const int i0 = (blockIdx.x % (NN / TI)) * TI;
    const int t  = threadIdx.x;

    s2s[t]       = g_s2[b * NN + t];
    s2s[t + 256] = g_s2[b * NN + t + 256];
    __syncthreads();

    const int w = t >> 5, lane = t & 31;
    {
        const int i = i0 + w;
        const float s1v = g_s1[b * NN + i];
        const int* adjrow = adj + (size_t)(b * NN + i) * NN;

        float m = -INFINITY;
        #pragma unroll
        for (int jj = 0; jj < 16; jj++) {
            const int j = lane + jj * 32;
            const float x = s1v + s2s[j];
            const float e = x > 0.f ? x : SLOPE * x;
            const float v = (adjrow[j] > 0) ? e : NEGV;
            att[w][j] = v;
            m = fmaxf(m, v);
        }
        #pragma unroll
        for (int off = 16; off; off >>= 1)
            m = fmaxf(m, __shfl_xor_sync(0xFFFFFFFFu, m, off));

        float s = 0.f;
        #pragma unroll
        for (int jj = 0; jj < 16; jj++) {
            const int j = lane + jj * 32;
            const float ex = __expf(att[w][j] - m);
            att[w][j] = ex;
            s += ex;
        }
        #pragma unroll
        for (int off = 16; off; off >>= 1)
            s += __shfl_xor_sync(0xFFFFFFFFu, s, off);

        const float inv = 1.f / s;
        float* arow = out_att + (size_t)(b * NN + i) * NN;
        #pragma unroll
        for (int jj = 0; jj < 16; jj++) {
            const int j = lane + jj * 32;
            const float av = att[w][j] * inv;
            att[w][j] = av;
            arow[j] = av;
        }
    }
    __syncthreads();

    // AV: thread t owns output column d = t for all 8 rows
    float acc[TI] = {};
    const float* WhB = g_Wh + (size_t)b * NN * DOUT + t;
    #pragma unroll 4
    for (int j = 0; j < NN; j++) {
        const float wv = WhB[(size_t)j * DOUT];
        #pragma unroll
        for (int r = 0; r < TI; r++)
            acc[r] += att[r][j] * wv;
    }
    #pragma unroll
    for (int r = 0; r < TI; r++)
        out_hp[(size_t)(b * NN + i0 + r) * DOUT + t] = acc[r];
}

// ---------------------------------------------------------------------------
extern "C" void kernel_launch(void* const* d_in, const int* in_sizes, int n_in,
                              void* d_out, int out_size)
{
    const float* h         = (const float*)d_in[0];
    const int*   adj       = (const int*)  d_in[1];
    const int*   positions = (const int*)  d_in[2];
    const float* W         = (const float*)d_in[3];
    const float* a1        = (const float*)d_in[4];
    const float* a2        = (const float*)d_in[5];
    const float* pos_table = (const float*)d_in[6];

    float* out_hp  = (float*)d_out;                        // [B,N,DOUT]
    float* out_att = (float*)d_out + (size_t)MM * DOUT;    // [B,N,N]

    k_gemm1<<<(MM / BM) * (DOUT / BN), 256>>>(h, positions, W, pos_table);
    k_sdots<<<MM / 8, 256>>>(a1, a2);
    k_attn<<<BB * (NN / 8), 256>>>(adj, out_hp, out_att);
}

// round 7
// speedup vs baseline: 3.3813x; 2.2383x over previous
#include <cuda_runtime.h>
#include <cuda_bf16.h>
#include <math.h>
#include <stdint.h>

// Problem constants
#define BB   32
#define NN   512
#define DIN  768
#define DOUT 256
#define MM   (BB * NN)          // 16384 rows
#define NEGV (-9.0e15f)
#define SLOPE 0.2f

// Scratch (device globals: allocation-free)
__device__ float g_Wh[(size_t)MM * DOUT];   // 16 MB
__device__ float g_s1[MM];
__device__ float g_s2[MM];

// ---------------------------------------------------------------------------
// tf32 helpers
// ---------------------------------------------------------------------------
__device__ __forceinline__ float to_tf32(float x) {
    asm("cvt.rna.tf32.f32 %0, %0;" : "+f"(x));
    return x;
}

__device__ __forceinline__ void mma_tf32(
    float c[4], unsigned a0, unsigned a1, unsigned a2, unsigned a3,
    unsigned b0, unsigned b1)
{
    asm volatile(
        "mma.sync.aligned.m16n8k8.row.col.f32.tf32.tf32.f32 "
        "{%0,%1,%2,%3}, {%4,%5,%6,%7}, {%8,%9}, {%0,%1,%2,%3};\n"
        : "+f"(c[0]), "+f"(c[1]), "+f"(c[2]), "+f"(c[3])
        : "r"(a0), "r"(a1), "r"(a2), "r"(a3), "r"(b0), "r"(b1));
}

// ---------------------------------------------------------------------------
// Kernel A: Wh = h @ W + pos_table[positions]  via tf32 tensor-core MMA
// C[16384,256] = A[16384,768] * W[768,256]
// BM=128 BN=128 BK=32, 256 threads = 8 warps (4 m x 2 n), warp tile 32x64.
// ---------------------------------------------------------------------------
#define BM 128
#define BN 128
#define BK 32
#define ASTRIDE 36     // BK + 4 : A-frag loads conflict-free (4*gid + tid4)
#define BSTRIDE 136    // BN + 8 : B-frag loads conflict-free (8*tid4 + gid)

__global__ void __launch_bounds__(256, 2) k_gemm1(
    const float* __restrict__ h,
    const int*   __restrict__ positions,
    const float* __restrict__ W,
    const float* __restrict__ pos_table)
{
    __shared__ float As[BM][ASTRIDE];
    __shared__ float Bs[BK][BSTRIDE];

    const int bx   = blockIdx.x;
    const int row0 = (bx >> 1) * BM;
    const int col0 = (bx & 1)  * BN;

    const int t    = threadIdx.x;
    const int wid  = t >> 5;
    const int lane = t & 31;
    const int gid  = lane >> 2;
    const int tid4 = lane & 3;

    const int wm = (wid & 3) * 32;
    const int wn = (wid >> 2) * 64;

    float acc[2][8][4];
    #pragma unroll
    for (int i = 0; i < 2; i++)
        #pragma unroll
        for (int j = 0; j < 8; j++)
            #pragma unroll
            for (int q = 0; q < 4; q++)
                acc[i][j][q] = 0.f;

    float4 ar[4], br[4];

    const int a_m  = t >> 3;
    const int a_k4 = (t & 7) * 4;
    const int b_kr = t >> 5;
    const int b_n4 = (t & 31) * 4;

    {
        const int k0 = 0;
        #pragma unroll
        for (int i = 0; i < 4; i++) {
            ar[i] = *reinterpret_cast<const float4*>(
                &h[(size_t)(row0 + a_m + i * 32) * DIN + k0 + a_k4]);
            br[i] = *reinterpret_cast<const float4*>(
                &W[(size_t)(k0 + b_kr + i * 8) * DOUT + col0 + b_n4]);
        }
    }

    const int NTILES = DIN / BK;   // 24
    for (int tile = 0; tile < NTILES; tile++) {
        #pragma unroll
        for (int i = 0; i < 4; i++) {
            float4 v = ar[i];
            v.x = to_tf32(v.x); v.y = to_tf32(v.y);
            v.z = to_tf32(v.z); v.w = to_tf32(v.w);
            *reinterpret_cast<float4*>(&As[a_m + i * 32][a_k4]) = v;
            float4 w4 = br[i];
            w4.x = to_tf32(w4.x); w4.y = to_tf32(w4.y);
            w4.z = to_tf32(w4.z); w4.w = to_tf32(w4.w);
            *reinterpret_cast<float4*>(&Bs[b_kr + i * 8][b_n4]) = w4;
        }
        __syncthreads();

        if (tile + 1 < NTILES) {
            const int k0 = (tile + 1) * BK;
            #pragma unroll
            for (int i = 0; i < 4; i++) {
                ar[i] = *reinterpret_cast<const float4*>(
                    &h[(size_t)(row0 + a_m + i * 32) * DIN + k0 + a_k4]);
                br[i] = *reinterpret_cast<const float4*>(
                    &W[(size_t)(k0 + b_kr + i * 8) * DOUT + col0 + b_n4]);
            }
        }

        #pragma unroll
        for (int ks = 0; ks < 4; ks++) {
            const int k8 = ks * 8;
            unsigned af[2][4];
            #pragma unroll
            for (int ms = 0; ms < 2; ms++) {
                const int r = wm + ms * 16 + gid;
                af[ms][0] = __float_as_uint(As[r    ][k8 + tid4]);
                af[ms][1] = __float_as_uint(As[r + 8][k8 + tid4]);
                af[ms][2] = __float_as_uint(As[r    ][k8 + tid4 + 4]);
                af[ms][3] = __float_as_uint(As[r + 8][k8 + tid4 + 4]);
            }
            #pragma unroll
            for (int ns = 0; ns < 8; ns++) {
                const int c = wn + ns * 8 + gid;
                unsigned b0 = __float_as_uint(Bs[k8 + tid4    ][c]);
                unsigned b1 = __float_as_uint(Bs[k8 + tid4 + 4][c]);
                mma_tf32(acc[0][ns], af[0][0], af[0][1], af[0][2], af[0][3], b0, b1);
                mma_tf32(acc[1][ns], af[1][0], af[1][1], af[1][2], af[1][3], b0, b1);
            }
        }
        __syncthreads();
    }

    #pragma unroll
    for (int ms = 0; ms < 2; ms++) {
        const int r0 = row0 + wm + ms * 16 + gid;
        const int r1 = r0 + 8;
        const int p0 = positions[r0];
        const int p1 = positions[r1];
        #pragma unroll
        for (int ns = 0; ns < 8; ns++) {
            const int c = col0 + wn + ns * 8 + tid4 * 2;
            float2 pe0 = *reinterpret_cast<const float2*>(&pos_table[(size_t)p0 * DOUT + c]);
            float2 pe1 = *reinterpret_cast<const float2*>(&pos_table[(size_t)p1 * DOUT + c]);
            float2 o0, o1;
            o0.x = acc[ms][ns][0] + pe0.x;
            o0.y = acc[ms][ns][1] + pe0.y;
            o1.x = acc[ms][ns][2] + pe1.x;
            o1.y = acc[ms][ns][3] + pe1.y;
            *reinterpret_cast<float2*>(&g_Wh[(size_t)r0 * DOUT + c]) = o0;
            *reinterpret_cast<float2*>(&g_Wh[(size_t)r1 * DOUT + c]) = o1;
        }
    }
}

// ---------------------------------------------------------------------------
// Kernel S: s1[row] = Wh[row,:] . a1 ; s2[row] = Wh[row,:] . a2
// ---------------------------------------------------------------------------
__global__ void __launch_bounds__(256) k_sdots(
    const float* __restrict__ a1,
    const float* __restrict__ a2)
{
    const int gwarp = (blockIdx.x * blockDim.x + threadIdx.x) >> 5;
    const int lane  = threadIdx.x & 31;
    if (gwarp >= MM) return;

    const float* wh = g_Wh + (size_t)gwarp * DOUT;
    float p1 = 0.f, p2 = 0.f;
    #pragma unroll
    for (int i = 0; i < 8; i++) {
        const int c = lane + i * 32;
        const float v = wh[c];
        p1 += v * a1[c];
        p2 += v * a2[c];
    }
    #pragma unroll
    for (int off = 16; off; off >>= 1) {
        p1 += __shfl_xor_sync(0xFFFFFFFFu, p1, off);
        p2 += __shfl_xor_sync(0xFFFFFFFFu, p2, off);
    }
    if (lane == 0) {
        g_s1[gwarp] = p1;
        g_s2[gwarp] = p2;
    }
}

// ---------------------------------------------------------------------------
// Kernel SM: masked softmax only.  One block = (batch b, 8 rows); warp per
// row; values live in registers (16 per lane). Writes out_att.
// ---------------------------------------------------------------------------
__global__ void __launch_bounds__(256) k_softmax(
    const int* __restrict__ adj,
    float* __restrict__ out_att)
{
    __shared__ float s2s[NN];

    const int b  = blockIdx.x >> 6;            // / 64
    const int i0 = (blockIdx.x & 63) * 8;
    const int t  = threadIdx.x;

    s2s[t]       = g_s2[b * NN + t];
    s2s[t + 256] = g_s2[b * NN + t + 256];
    __syncthreads();

    const int w = t >> 5, lane = t & 31;
    const int i = i0 + w;
    const float s1v = g_s1[b * NN + i];
    const int* adjrow = adj + (size_t)(b * NN + i) * NN;

    float v[16];
    float m = -INFINITY;
    #pragma unroll
    for (int jj = 0; jj < 16; jj++) {
        const int j = lane + jj * 32;
        const float x = s1v + s2s[j];
        const float e = x > 0.f ? x : SLOPE * x;
        const float val = (adjrow[j] > 0) ? e : NEGV;
        v[jj] = val;
        m = fmaxf(m, val);
    }
    #pragma unroll
    for (int off = 16; off; off >>= 1)
        m = fmaxf(m, __shfl_xor_sync(0xFFFFFFFFu, m, off));

    float s = 0.f;
    #pragma unroll
    for (int jj = 0; jj < 16; jj++) {
        const float ex = __expf(v[jj] - m);
        v[jj] = ex;
        s += ex;
    }
    #pragma unroll
    for (int off = 16; off; off >>= 1)
        s += __shfl_xor_sync(0xFFFFFFFFu, s, off);

    const float inv = 1.f / s;
    float* arow = out_att + (size_t)(b * NN + i) * NN;
    #pragma unroll
    for (int jj = 0; jj < 16; jj++)
        arow[lane + jj * 32] = v[jj] * inv;
}

// ---------------------------------------------------------------------------
// Kernel G2: h_prime[b] = att[b] @ Wh[b]  via tf32 MMA (batched)
// per batch: C[512,256] = A[512,512] * B[512,256]
// Same tile scheme as k_gemm1: BM=128 BN=128 BK=32, 8 warps.
// grid = 32 * 4 * 2 = 256 blocks
// ---------------------------------------------------------------------------
__global__ void __launch_bounds__(256, 2) k_gemm2(
    const float* __restrict__ att,
    float* __restrict__ out_hp)
{
    __shared__ float As[BM][ASTRIDE];
    __shared__ float Bs[BK][BSTRIDE];

    const int bx   = blockIdx.x;
    const int b    = bx >> 3;
    const int tile = bx & 7;
    const int row0 = (tile >> 1) * BM;
    const int col0 = (tile & 1)  * BN;

    const float* A = att  + (size_t)b * NN * NN;      // [512,512]
    const float* Bm = g_Wh + (size_t)b * NN * DOUT;   // [512,256]

    const int t    = threadIdx.x;
    const int wid  = t >> 5;
    const int lane = t & 31;
    const int gid  = lane >> 2;
    const int tid4 = lane & 3;

    const int wm = (wid & 3) * 32;
    const int wn = (wid >> 2) * 64;

    float acc[2][8][4];
    #pragma unroll
    for (int i = 0; i < 2; i++)
        #pragma unroll
        for (int j = 0; j < 8; j++)
            #pragma unroll
            for (int q = 0; q < 4; q++)
                acc[i][j][q] = 0.f;

    float4 ar[4], br[4];

    const int a_m  = t >> 3;
    const int a_k4 = (t & 7) * 4;
    const int b_kr = t >> 5;
    const int b_n4 = (t & 31) * 4;

    {
        const int k0 = 0;
        #pragma unroll
        for (int i = 0; i < 4; i++) {
            ar[i] = *reinterpret_cast<const float4*>(
                &A[(size_t)(row0 + a_m + i * 32) * NN + k0 + a_k4]);
            br[i] = *reinterpret_cast<const float4*>(
                &Bm[(size_t)(k0 + b_kr + i * 8) * DOUT + col0 + b_n4]);
        }
    }

    const int NTILES = NN / BK;    // 16
    for (int tile_k = 0; tile_k < NTILES; tile_k++) {
        #pragma unroll
        for (int i = 0; i < 4; i++) {
            float4 v = ar[i];
            v.x = to_tf32(v.x); v.y = to_tf32(v.y);
            v.z = to_tf32(v.z); v.w = to_tf32(v.w);
            *reinterpret_cast<float4*>(&As[a_m + i * 32][a_k4]) = v;
            float4 w4 = br[i];
            w4.x = to_tf32(w4.x); w4.y = to_tf32(w4.y);
            w4.z = to_tf32(w4.z); w4.w = to_tf32(w4.w);
            *reinterpret_cast<float4*>(&Bs[b_kr + i * 8][b_n4]) = w4;
        }
        __syncthreads();

        if (tile_k + 1 < NTILES) {
            const int k0 = (tile_k + 1) * BK;
            #pragma unroll
            for (int i = 0; i < 4; i++) {
                ar[i] = *reinterpret_cast<const float4*>(
                    &A[(size_t)(row0 + a_m + i * 32) * NN + k0 + a_k4]);
                br[i] = *reinterpret_cast<const float4*>(
                    &Bm[(size_t)(k0 + b_kr + i * 8) * DOUT + col0 + b_n4]);
            }
        }

        #pragma unroll
        for (int ks = 0; ks < 4; ks++) {
            const int k8 = ks * 8;
            unsigned af[2][4];
            #pragma unroll
            for (int ms = 0; ms < 2; ms++) {
                const int r = wm + ms * 16 + gid;
                af[ms][0] = __float_as_uint(As[r    ][k8 + tid4]);
                af[ms][1] = __float_as_uint(As[r + 8][k8 + tid4]);
                af[ms][2] = __float_as_uint(As[r    ][k8 + tid4 + 4]);
                af[ms][3] = __float_as_uint(As[r + 8][k8 + tid4 + 4]);
            }
            #pragma unroll
            for (int ns = 0; ns < 8; ns++) {
                const int c = wn + ns * 8 + gid;
                unsigned b0 = __float_as_uint(Bs[k8 + tid4    ][c]);
                unsigned b1 = __float_as_uint(Bs[k8 + tid4 + 4][c]);
                mma_tf32(acc[0][ns], af[0][0], af[0][1], af[0][2], af[0][3], b0, b1);
                mma_tf32(acc[1][ns], af[1][0], af[1][1], af[1][2], af[1][3], b0, b1);
            }
        }
        __syncthreads();
    }

    float* outB = out_hp + (size_t)b * NN * DOUT;
    #pragma unroll
    for (int ms = 0; ms < 2; ms++) {
        const int r0 = row0 + wm + ms * 16 + gid;
        const int r1 = r0 + 8;
        #pragma unroll
        for (int ns = 0; ns < 8; ns++) {
            const int c = col0 + wn + ns * 8 + tid4 * 2;
            float2 o0, o1;
            o0.x = acc[ms][ns][0];
            o0.y = acc[ms][ns][1];
            o1.x = acc[ms][ns][2];
            o1.y = acc[ms][ns][3];
            *reinterpret_cast<float2*>(&outB[(size_t)r0 * DOUT + c]) = o0;
            *reinterpret_cast<float2*>(&outB[(size_t)r1 * DOUT + c]) = o1;
        }
    }
}

// ---------------------------------------------------------------------------
extern "C" void kernel_launch(void* const* d_in, const int* in_sizes, int n_in,
                              void* d_out, int out_size)
{
    const float* h         = (const float*)d_in[0];
    const int*   adj       = (const int*)  d_in[1];
    const int*   positions = (const int*)  d_in[2];
    const float* W         = (const float*)d_in[3];
    const float* a1        = (const float*)d_in[4];
    const float* a2        = (const float*)d_in[5];
    const float* pos_table = (const float*)d_in[6];

    float* out_hp  = (float*)d_out;                        // [B,N,DOUT]
    float* out_att = (float*)d_out + (size_t)MM * DOUT;    // [B,N,N]

    k_gemm1<<<(MM / BM) * (DOUT / BN), 256>>>(h, positions, W, pos_table);
    k_sdots<<<MM / 8, 256>>>(a1, a2);
    k_softmax<<<BB * (NN / 8), 256>>>(adj, out_att);
    k_gemm2<<<BB * 8, 256>>>(out_att, out_hp);
}

// round 8
// speedup vs baseline: 3.3823x; 1.0003x over previous
#include <cuda_runtime.h>
#include <cuda_bf16.h>
#include <math.h>
#include <stdint.h>

// Problem constants
#define BB   32
#define NN   512
#define DIN  768
#define DOUT 256
#define MM   (BB * NN)          // 16384 rows
#define NEGV (-9.0e15f)
#define SLOPE 0.2f

// Scratch (device globals: allocation-free)
__device__ float g_Wh[(size_t)MM * DOUT];   // 16 MB
__device__ float g_s1[MM];
__device__ float g_s2[MM];

// ---------------------------------------------------------------------------
// tf32 helpers
// ---------------------------------------------------------------------------
__device__ __forceinline__ float to_tf32(float x) {
    asm("cvt.rna.tf32.f32 %0, %0;" : "+f"(x));
    return x;
}

__device__ __forceinline__ void mma_tf32(
    float c[4], unsigned a0, unsigned a1, unsigned a2, unsigned a3,
    unsigned b0, unsigned b1)
{
    asm volatile(
        "mma.sync.aligned.m16n8k8.row.col.f32.tf32.tf32.f32 "
        "{%0,%1,%2,%3}, {%4,%5,%6,%7}, {%8,%9}, {%0,%1,%2,%3};\n"
        : "+f"(c[0]), "+f"(c[1]), "+f"(c[2]), "+f"(c[3])
        : "r"(a0), "r"(a1), "r"(a2), "r"(a3), "r"(b0), "r"(b1));
}

// ---------------------------------------------------------------------------
// Shared GEMM tile geometry
// BM=128 BN=128 BK=32, 256 threads = 8 warps (4 m x 2 n), warp tile 32x64.
// Double-buffered smem: 2 stages of (As + Bs).
// ---------------------------------------------------------------------------
#define BM 128
#define BN 128
#define BK 32
#define ASTRIDE 36     // BK + 4 : A-frag loads conflict-free
#define BSTRIDE 136    // BN + 8 : B-frag loads conflict-free
#define AS_FLOATS (BM * ASTRIDE)                 // 4608
#define BS_FLOATS (BK * BSTRIDE)                 // 4352
#define STAGE_FLOATS (AS_FLOATS + BS_FLOATS)     // 8960
#define SMEM_BYTES (2 * STAGE_FLOATS * 4)        // 71680

// store staged regs (with tf32 rounding) into a given stage
__device__ __forceinline__ void stage_store(
    float* stage, const float4* ar, const float4* br,
    int a_m, int a_k4, int b_kr, int b_n4)
{
    float (*As)[ASTRIDE] = reinterpret_cast<float (*)[ASTRIDE]>(stage);
    float (*Bs)[BSTRIDE] = reinterpret_cast<float (*)[BSTRIDE]>(stage + AS_FLOATS);
    #pragma unroll
    for (int i = 0; i < 4; i++) {
        float4 v = ar[i];
        v.x = to_tf32(v.x); v.y = to_tf32(v.y);
        v.z = to_tf32(v.z); v.w = to_tf32(v.w);
        *reinterpret_cast<float4*>(&As[a_m + i * 32][a_k4]) = v;
        float4 w4 = br[i];
        w4.x = to_tf32(w4.x); w4.y = to_tf32(w4.y);
        w4.z = to_tf32(w4.z); w4.w = to_tf32(w4.w);
        *reinterpret_cast<float4*>(&Bs[b_kr + i * 8][b_n4]) = w4;
    }
}

// run the 4 k-steps of MMAs for one stage
__device__ __forceinline__ void stage_mma(
    const float* stage, float acc[2][8][4],
    int wm, int wn, int gid, int tid4)
{
    const float (*As)[ASTRIDE] =
        reinterpret_cast<const float (*)[ASTRIDE]>(stage);
    const float (*Bs)[BSTRIDE] =
        reinterpret_cast<const float (*)[BSTRIDE]>(stage + AS_FLOATS);
    #pragma unroll
    for (int ks = 0; ks < 4; ks++) {
        const int k8 = ks * 8;
        unsigned af[2][4];
        #pragma unroll
        for (int ms = 0; ms < 2; ms++) {
            const int r = wm + ms * 16 + gid;
            af[ms][0] = __float_as_uint(As[r    ][k8 + tid4]);
            af[ms][1] = __float_as_uint(As[r + 8][k8 + tid4]);
            af[ms][2] = __float_as_uint(As[r    ][k8 + tid4 + 4]);
            af[ms][3] = __float_as_uint(As[r + 8][k8 + tid4 + 4]);
        }
        #pragma unroll
        for (int ns = 0; ns < 8; ns++) {
            const int c = wn + ns * 8 + gid;
            unsigned b0 = __float_as_uint(Bs[k8 + tid4    ][c]);
            unsigned b1 = __float_as_uint(Bs[k8 + tid4 + 4][c]);
            mma_tf32(acc[0][ns], af[0][0], af[0][1], af[0][2], af[0][3], b0, b1);
            mma_tf32(acc[1][ns], af[1][0], af[1][1], af[1][2], af[1][3], b0, b1);
        }
    }
}

// ---------------------------------------------------------------------------
// Kernel A: Wh = h @ W + pos_table[positions]  via tf32 MMA, 2-stage pipeline
// C[16384,256] = A[16384,768] * W[768,256]
// ---------------------------------------------------------------------------
__global__ void __launch_bounds__(256, 2) k_gemm1(
    const float* __restrict__ h,
    const int*   __restrict__ positions,
    const float* __restrict__ W,
    const float* __restrict__ pos_table)
{
    extern __shared__ float smem[];

    const int bx   = blockIdx.x;
    const int row0 = (bx >> 1) * BM;
    const int col0 = (bx & 1)  * BN;

    const int t    = threadIdx.x;
    const int wid  = t >> 5;
    const int lane = t & 31;
    const int gid  = lane >> 2;
    const int tid4 = lane & 3;
    const int wm = (wid & 3) * 32;
    const int wn = (wid >> 2) * 64;

    float acc[2][8][4];
    #pragma unroll
    for (int i = 0; i < 2; i++)
        #pragma unroll
        for (int j = 0; j < 8; j++)
            #pragma unroll
            for (int q = 0; q < 4; q++)
                acc[i][j][q] = 0.f;

    float4 ar[4], br[4];
    const int a_m  = t >> 3;
    const int a_k4 = (t & 7) * 4;
    const int b_kr = t >> 5;
    const int b_n4 = (t & 31) * 4;

    const int NTILES = DIN / BK;   // 24

    // prologue: tile0 -> stage0; tile1 -> regs
    #pragma unroll
    for (int i = 0; i < 4; i++) {
        ar[i] = *reinterpret_cast<const float4*>(
            &h[(size_t)(row0 + a_m + i * 32) * DIN + a_k4]);
        br[i] = *reinterpret_cast<const float4*>(
            &W[(size_t)(b_kr + i * 8) * DOUT + col0 + b_n4]);
    }
    stage_store(smem, ar, br, a_m, a_k4, b_kr, b_n4);
    #pragma unroll
    for (int i = 0; i < 4; i++) {
        ar[i] = *reinterpret_cast<const float4*>(
            &h[(size_t)(row0 + a_m + i * 32) * DIN + BK + a_k4]);
        br[i] = *reinterpret_cast<const float4*>(
            &W[(size_t)(BK + b_kr + i * 8) * DOUT + col0 + b_n4]);
    }
    __syncthreads();

    for (int tile = 0; tile < NTILES; tile++) {
        float* cur = smem + (tile & 1) * STAGE_FLOATS;
        if (tile + 1 < NTILES) {
            float* nxt = smem + ((tile + 1) & 1) * STAGE_FLOATS;
            stage_store(nxt, ar, br, a_m, a_k4, b_kr, b_n4);
        }
        if (tile + 2 < NTILES) {
            const int k0 = (tile + 2) * BK;
            #pragma unroll
            for (int i = 0; i < 4; i++) {
                ar[i] = *reinterpret_cast<const float4*>(
                    &h[(size_t)(row0 + a_m + i * 32) * DIN + k0 + a_k4]);
                br[i] = *reinterpret_cast<const float4*>(
                    &W[(size_t)(k0 + b_kr + i * 8) * DOUT + col0 + b_n4]);
            }
        }
        stage_mma(cur, acc, wm, wn, gid, tid4);
        __syncthreads();
    }

    // epilogue: add positional embedding, store Wh
    #pragma unroll
    for (int ms = 0; ms < 2; ms++) {
        const int r0 = row0 + wm + ms * 16 + gid;
        const int r1 = r0 + 8;
        const int p0 = positions[r0];
        const int p1 = positions[r1];
        #pragma unroll
        for (int ns = 0; ns < 8; ns++) {
            const int c = col0 + wn + ns * 8 + tid4 * 2;
            float2 pe0 = *reinterpret_cast<const float2*>(&pos_table[(size_t)p0 * DOUT + c]);
            float2 pe1 = *reinterpret_cast<const float2*>(&pos_table[(size_t)p1 * DOUT + c]);
            float2 o0, o1;
            o0.x = acc[ms][ns][0] + pe0.x;
            o0.y = acc[ms][ns][1] + pe0.y;
            o1.x = acc[ms][ns][2] + pe1.x;
            o1.y = acc[ms][ns][3] + pe1.y;
            *reinterpret_cast<float2*>(&g_Wh[(size_t)r0 * DOUT + c]) = o0;
            *reinterpret_cast<float2*>(&g_Wh[(size_t)r1 * DOUT + c]) = o1;
        }
    }
}

// ---------------------------------------------------------------------------
// Kernel S: s1[row] = Wh[row,:] . a1 ; s2[row] = Wh[row,:] . a2
// ---------------------------------------------------------------------------
__global__ void __launch_bounds__(256) k_sdots(
    const float* __restrict__ a1,
    const float* __restrict__ a2)
{
    const int gwarp = (blockIdx.x * blockDim.x + threadIdx.x) >> 5;
    const int lane  = threadIdx.x & 31;
    if (gwarp >= MM) return;

    const float* wh = g_Wh + (size_t)gwarp * DOUT;
    float p1 = 0.f, p2 = 0.f;
    #pragma unroll
    for (int i = 0; i < 8; i++) {
        const int c = lane + i * 32;
        const float v = wh[c];
        p1 += v * a1[c];
        p2 += v * a2[c];
    }
    #pragma unroll
    for (int off = 16; off; off >>= 1) {
        p1 += __shfl_xor_sync(0xFFFFFFFFu, p1, off);
        p2 += __shfl_xor_sync(0xFFFFFFFFu, p2, off);
    }
    if (lane == 0) {
        g_s1[gwarp] = p1;
        g_s2[gwarp] = p2;
    }
}

// ---------------------------------------------------------------------------
// Kernel SM: masked softmax only.  One block = (batch b, 8 rows); warp per
// row; values live in registers (16 per lane). Writes out_att.
// ---------------------------------------------------------------------------
__global__ void __launch_bounds__(256) k_softmax(
    const int* __restrict__ adj,
    float* __restrict__ out_att)
{
    __shared__ float s2s[NN];

    const int b  = blockIdx.x >> 6;
    const int i0 = (blockIdx.x & 63) * 8;
    const int t  = threadIdx.x;

    s2s[t]       = g_s2[b * NN + t];
    s2s[t + 256] = g_s2[b * NN + t + 256];
    __syncthreads();

    const int w = t >> 5, lane = t & 31;
    const int i = i0 + w;
    const float s1v = g_s1[b * NN + i];
    const int* adjrow = adj + (size_t)(b * NN + i) * NN;

    float v[16];
    float m = -INFINITY;
    #pragma unroll
    for (int jj = 0; jj < 16; jj++) {
        const int j = lane + jj * 32;
        const float x = s1v + s2s[j];
        const float e = x > 0.f ? x : SLOPE * x;
        const float val = (adjrow[j] > 0) ? e : NEGV;
        v[jj] = val;
        m = fmaxf(m, val);
    }
    #pragma unroll
    for (int off = 16; off; off >>= 1)
        m = fmaxf(m, __shfl_xor_sync(0xFFFFFFFFu, m, off));

    float s = 0.f;
    #pragma unroll
    for (int jj = 0; jj < 16; jj++) {
        const float ex = __expf(v[jj] - m);
        v[jj] = ex;
        s += ex;
    }
    #pragma unroll
    for (int off = 16; off; off >>= 1)
        s += __shfl_xor_sync(0xFFFFFFFFu, s, off);

    const float inv = 1.f / s;
    float* arow = out_att + (size_t)(b * NN + i) * NN;
    #pragma unroll
    for (int jj = 0; jj < 16; jj++)
        arow[lane + jj * 32] = v[jj] * inv;
}

// ---------------------------------------------------------------------------
// Kernel G2: h_prime[b] = att[b] @ Wh[b]  via tf32 MMA, 2-stage pipeline
// per batch: C[512,256] = A[512,512] * B[512,256]
// ---------------------------------------------------------------------------
__global__ void __launch_bounds__(256, 2) k_gemm2(
    const float* __restrict__ att,
    float* __restrict__ out_hp)
{
    extern __shared__ float smem[];

    const int bx   = blockIdx.x;
    const int b    = bx >> 3;
    const int tile = bx & 7;
    const int row0 = (tile >> 1) * BM;
    const int col0 = (tile & 1)  * BN;

    const float* A  = att  + (size_t)b * NN * NN;
    const float* Bm = g_Wh + (size_t)b * NN * DOUT;

    const int t    = threadIdx.x;
    const int wid  = t >> 5;
    const int lane = t & 31;
    const int gid  = lane >> 2;
    const int tid4 = lane & 3;
    const int wm = (wid & 3) * 32;
    const int wn = (wid >> 2) * 64;

    float acc[2][8][4];
    #pragma unroll
    for (int i = 0; i < 2; i++)
        #pragma unroll
        for (int j = 0; j < 8; j++)
            #pragma unroll
            for (int q = 0; q < 4; q++)
                acc[i][j][q] = 0.f;

    float4 ar[4], br[4];
    const int a_m  = t >> 3;
    const int a_k4 = (t & 7) * 4;
    const int b_kr = t >> 5;
    const int b_n4 = (t & 31) * 4;

    const int NTILES = NN / BK;    // 16

    #pragma unroll
    for (int i = 0; i < 4; i++) {
        ar[i] = *reinterpret_cast<const float4*>(
            &A[(size_t)(row0 + a_m + i * 32) * NN + a_k4]);
        br[i] = *reinterpret_cast<const float4*>(
            &Bm[(size_t)(b_kr + i * 8) * DOUT + col0 + b_n4]);
    }
    stage_store(smem, ar, br, a_m, a_k4, b_kr, b_n4);
    #pragma unroll
    for (int i = 0; i < 4; i++) {
        ar[i] = *reinterpret_cast<const float4*>(
            &A[(size_t)(row0 + a_m + i * 32) * NN + BK + a_k4]);
        br[i] = *reinterpret_cast<const float4*>(
            &Bm[(size_t)(BK + b_kr + i * 8) * DOUT + col0 + b_n4]);
    }
    __syncthreads();

    for (int tk = 0; tk < NTILES; tk++) {
        float* cur = smem + (tk & 1) * STAGE_FLOATS;
        if (tk + 1 < NTILES) {
            float* nxt = smem + ((tk + 1) & 1) * STAGE_FLOATS;
            stage_store(nxt, ar, br, a_m, a_k4, b_kr, b_n4);
        }
        if (tk + 2 < NTILES) {
            const int k0 = (tk + 2) * BK;
            #pragma unroll
            for (int i = 0; i < 4; i++) {
                ar[i] = *reinterpret_cast<const float4*>(
                    &A[(size_t)(row0 + a_m + i * 32) * NN + k0 + a_k4]);
                br[i] = *reinterpret_cast<const float4*>(
                    &Bm[(size_t)(k0 + b_kr + i * 8) * DOUT + col0 + b_n4]);
            }
        }
        stage_mma(cur, acc, wm, wn, gid, tid4);
        __syncthreads();
    }

    float* outB = out_hp + (size_t)b * NN * DOUT;
    #pragma unroll
    for (int ms = 0; ms < 2; ms++) {
        const int r0 = row0 + wm + ms * 16 + gid;
        const int r1 = r0 + 8;
        #pragma unroll
        for (int ns = 0; ns < 8; ns++) {
            const int c = col0 + wn + ns * 8 + tid4 * 2;
            float2 o0, o1;
            o0.x = acc[ms][ns][0];
            o0.y = acc[ms][ns][1];
            o1.x = acc[ms][ns][2];
            o1.y = acc[ms][ns][3];
            *reinterpret_cast<float2*>(&outB[(size_t)r0 * DOUT + c]) = o0;
            *reinterpret_cast<float2*>(&outB[(size_t)r1 * DOUT + c]) = o1;
        }
    }
}

// ---------------------------------------------------------------------------
extern "C" void kernel_launch(void* const* d_in, const int* in_sizes, int n_in,
                              void* d_out, int out_size)
{
    const float* h         = (const float*)d_in[0];
    const int*   adj       = (const int*)  d_in[1];
    const int*   positions = (const int*)  d_in[2];
    const float* W         = (const float*)d_in[3];
    const float* a1        = (const float*)d_in[4];
    const float* a2        = (const float*)d_in[5];
    const float* pos_table = (const float*)d_in[6];

    float* out_hp  = (float*)d_out;                        // [B,N,DOUT]
    float* out_att = (float*)d_out + (size_t)MM * DOUT;    // [B,N,N]

    static bool attr_done = false;
    if (!attr_done) {
        cudaFuncSetAttribute(k_gemm1,
            cudaFuncAttributeMaxDynamicSharedMemorySize, SMEM_BYTES);
        cudaFuncSetAttribute(k_gemm2,
            cudaFuncAttributeMaxDynamicSharedMemorySize, SMEM_BYTES);
        attr_done = true;
    }

    k_gemm1<<<(MM / BM) * (DOUT / BN), 256, SMEM_BYTES>>>(h, positions, W, pos_table);
    k_sdots<<<MM / 8, 256>>>(a1, a2);
    k_softmax<<<BB * (NN / 8), 256>>>(adj, out_att);
    k_gemm2<<<BB * 8, 256, SMEM_BYTES>>>(out_att, out_hp);
}